// round 15
// baseline (speedup 1.0000x reference)
#include <cuda_runtime.h>
#include <stdint.h>

#define NMAX 50000
#define EMAX 600000
#define SCAN_BLK 2048
#define MAX_SBLK 32
#define ZERO_BLKS 64
#define WPREP_BLKS 144   // 3*64*128 + 3*64*64 = 36864 elems / 256

typedef unsigned long long ull;

// ---------------- CSR scratch ----------------
__device__ int g_cnt[3][NMAX + 1];
__device__ int g_rowfin[3][NMAX + 1];
__device__ int g_rank[3][EMAX];
__device__ int g_esrc[3][EMAX];
__device__ int g_bsum[3][MAX_SBLK];
__device__ int g_boff[3][MAX_SBLK];
__device__ int g_total[3];
__device__ int g_arrive[3];

// ---------------- interleaved weights ----------------
__device__ __align__(16) float2 g_w1i[3][64][128];   // (W1[2kk][j], W1[2kk+1][j])
__device__ __align__(16) float2 g_w2i[3][64][64];    // (W2[2kk][c], W2[2kk+1][c])

// ---------------- float scratch ----------------
constexpr size_t F_AGG0  = 0;                                   // [ND,128] mean(x) rel0
constexpr size_t F_AGG1  = F_AGG0  + (size_t)NMAX * 128;        // [NP,128] rel1
constexpr size_t F_AGG2  = F_AGG1  + (size_t)NMAX * 128;        // [NP,128] rel2
constexpr size_t F_HD    = F_AGG2  + (size_t)NMAX * 128;
constexpr size_t F_HP    = F_HD    + (size_t)NMAX * 128;
constexpr size_t F_T_DDI = F_HP    + (size_t)NMAX * 128;
constexpr size_t F_T_DPI = F_T_DDI + (size_t)NMAX * 64;
constexpr size_t F_T_PPI = F_T_DPI + (size_t)NMAX * 64;
constexpr size_t F_TOTAL = F_T_PPI + (size_t)NMAX * 64;
__device__ float g_fs[F_TOTAL];

// ---------------- packed f32x2 helpers ----------------
__device__ __forceinline__ ull ffma2(ull a, ull b, ull c) {
    ull d;
    asm("fma.rn.f32x2 %0, %1, %2, %3;" : "=l"(d) : "l"(a), "l"(b), "l"(c));
    return d;
}
__device__ __forceinline__ void unpack2(ull v, float& lo, float& hi) {
    asm("mov.b64 {%0, %1}, %2;" : "=f"(lo), "=f"(hi) : "l"(v));
}

// ---------------- CSR build + W interleave (launch 0) ----------------

__global__ void k_count(const int* __restrict__ d0, int e0,
                        const int* __restrict__ d1, int e1,
                        const int* __restrict__ d2, int e2,
                        const float* __restrict__ W1_ddi, const float* __restrict__ W1_dpi,
                        const float* __restrict__ W1_ppi,
                        const float* __restrict__ W2_ddi, const float* __restrict__ W2_dpi,
                        const float* __restrict__ W2_ppi,
                        int nb_count) {
    if ((int)blockIdx.x >= nb_count) {
        int t = (blockIdx.x - nb_count) * 256 + threadIdx.x;
        int n1 = 3 * 64 * 128;
        if (t < n1) {
            int rel = t / (64 * 128);
            int rem = t % (64 * 128);
            int kk = rem >> 7, j = rem & 127;
            const float* W = (rel == 0) ? W1_ddi : ((rel == 1) ? W1_dpi : W1_ppi);
            g_w1i[rel][kk][j] = make_float2(__ldg(W + (2 * kk) * 128 + j),
                                            __ldg(W + (2 * kk + 1) * 128 + j));
        } else if (t < n1 + 3 * 64 * 64) {
            int u = t - n1;
            int rel = u / (64 * 64);
            int rem = u % (64 * 64);
            int kk = rem >> 6, c = rem & 63;
            const float* W = (rel == 0) ? W2_ddi : ((rel == 1) ? W2_dpi : W2_ppi);
            g_w2i[rel][kk][c] = make_float2(__ldg(W + (2 * kk) * 64 + c),
                                            __ldg(W + (2 * kk + 1) * 64 + c));
        }
        return;
    }
    int i = blockIdx.x * 256 + threadIdx.x;
    int stride = nb_count * 256;
    for (int j = i; j < e0; j += stride)
        g_rank[0][j] = atomicAdd(&g_cnt[0][__ldg(d0 + j)], 1);
    for (int j = i; j < e1; j += stride)
        g_rank[1][j] = atomicAdd(&g_cnt[1][__ldg(d1 + j)], 1);
    for (int j = i; j < e2; j += stride)
        g_rank[2][j] = atomicAdd(&g_cnt[2][__ldg(d2 + j)], 1);
}

__global__ void __launch_bounds__(1024)
k_scan12(int sblk, int n0, int n1, int n2) {
    __shared__ int sh[1024];
    __shared__ bool is_last;
    int rel = blockIdx.x / sblk;
    int blk = blockIdx.x % sblk;
    int n = (rel == 0) ? n0 : ((rel == 1) ? n1 : n2);
    int* cnt = g_cnt[rel];
    int tid = threadIdx.x;
    int base = blk * SCAN_BLK + tid * 2;
    int c0 = (base < n)     ? cnt[base]     : 0;
    int c1 = (base + 1 < n) ? cnt[base + 1] : 0;
    sh[tid] = c0 + c1;
    __syncthreads();
    for (int off = 1; off < 1024; off <<= 1) {
        int v = (tid >= off) ? sh[tid - off] : 0;
        __syncthreads();
        sh[tid] += v;
        __syncthreads();
    }
    int toff = (tid > 0) ? sh[tid - 1] : 0;
    if (base < n)     cnt[base]     = toff;
    if (base + 1 < n) cnt[base + 1] = toff + c0;
    if (tid == 1023) g_bsum[rel][blk] = sh[1023];

    __threadfence();
    __syncthreads();
    if (tid == 0) {
        int old = atomicAdd(&g_arrive[rel], 1);
        is_last = (old == sblk - 1);
    }
    __syncthreads();
    if (is_last && tid < 32) {
        int v = (tid < sblk) ? g_bsum[rel][tid] : 0;
        int orig = v;
#pragma unroll
        for (int off = 1; off < 32; off <<= 1) {
            int u = __shfl_up_sync(0xFFFFFFFF, v, off);
            if (tid >= off) v += u;
        }
        if (tid < sblk) g_boff[rel][tid] = v - orig;
        if (tid == 31) {
            g_total[rel] = v;
            g_arrive[rel] = 0;
        }
    }
}

__global__ void k_fillfin(const int* __restrict__ s0, const int* __restrict__ d0, int e0,
                          const int* __restrict__ s1, const int* __restrict__ d1, int e1,
                          const int* __restrict__ s2, const int* __restrict__ d2, int e2,
                          int n0, int n1, int n2) {
    int i = blockIdx.x * blockDim.x + threadIdx.x;
    int stride = gridDim.x * blockDim.x;
    for (int e = i; e < e0; e += stride) {
        int d = __ldg(d0 + e);
        int pos = g_cnt[0][d] + g_boff[0][d >> 11] + g_rank[0][e];
        g_esrc[0][pos] = __ldg(s0 + e);
    }
    for (int e = i; e < e1; e += stride) {
        int d = __ldg(d1 + e);
        int pos = g_cnt[1][d] + g_boff[1][d >> 11] + g_rank[1][e];
        g_esrc[1][pos] = __ldg(s1 + e);
    }
    for (int e = i; e < e2; e += stride) {
        int d = __ldg(d2 + e);
        int pos = g_cnt[2][d] + g_boff[2][d >> 11] + g_rank[2][e];
        g_esrc[2][pos] = __ldg(s2 + e);
    }
    int totalf = 3 * (NMAX + 1);
    for (int t = i; t < totalf; t += stride) {
        int rel = t / (NMAX + 1);
        int idx = t % (NMAX + 1);
        int n = (rel == 0) ? n0 : ((rel == 1) ? n1 : n2);
        if (idx < n)
            g_rowfin[rel][idx] = g_cnt[rel][idx] + g_boff[rel][idx >> 11];
        else if (idx == n)
            g_rowfin[rel][n] = g_total[rel];
    }
}

// ---------------- gather primitives ----------------

__device__ __forceinline__ void node_range(const int* __restrict__ ptr, int node, int n,
                                           int& b, int& d) {
    if (node < n) {
        b = ptr[node];
        d = ptr[node + 1] - b;
    } else {
        b = 0; d = 0;
    }
}

__device__ __forceinline__ void gpair128(const int* __restrict__ es,
                                         const float* __restrict__ x,
                                         int b0, int d0, int b1, int d1, int lane,
                                         float4& o0, float4& o1) {
    float4 a0 = make_float4(0.f, 0.f, 0.f, 0.f);
    float4 a1 = make_float4(0.f, 0.f, 0.f, 0.f);
    int m = d0 > d1 ? d0 : d1;
    for (int e = 0; e < m; e += 4) {
        float4 v0[4], v1[4];
#pragma unroll
        for (int j = 0; j < 4; j++) {
            bool q0 = (e + j) < d0;
            bool q1 = (e + j) < d1;
            int s0 = q0 ? __ldg(es + b0 + e + j) : 0;
            int s1 = q1 ? __ldg(es + b1 + e + j) : 0;
            v0[j] = q0 ? __ldg(reinterpret_cast<const float4*>(x + (size_t)s0 * 128) + lane)
                       : make_float4(0.f, 0.f, 0.f, 0.f);
            v1[j] = q1 ? __ldg(reinterpret_cast<const float4*>(x + (size_t)s1 * 128) + lane)
                       : make_float4(0.f, 0.f, 0.f, 0.f);
        }
#pragma unroll
        for (int j = 0; j < 4; j++) {
            a0.x += v0[j].x; a0.y += v0[j].y; a0.z += v0[j].z; a0.w += v0[j].w;
            a1.x += v1[j].x; a1.y += v1[j].y; a1.z += v1[j].z; a1.w += v1[j].w;
        }
    }
    float i0 = 1.0f / fmaxf((float)d0, 1.0f);
    float i1 = 1.0f / fmaxf((float)d1, 1.0f);
    o0 = make_float4(a0.x * i0, a0.y * i0, a0.z * i0, a0.w * i0);
    o1 = make_float4(a1.x * i1, a1.y * i1, a1.z * i1, a1.w * i1);
}

__device__ __forceinline__ void gpair64(const int* __restrict__ es,
                                        const float* __restrict__ x,
                                        int b0, int d0, int b1, int d1, int lane,
                                        float2& o0, float2& o1) {
    float2 a0 = make_float2(0.f, 0.f);
    float2 a1 = make_float2(0.f, 0.f);
    int m = d0 > d1 ? d0 : d1;
    for (int e = 0; e < m; e += 4) {
        float2 v0[4], v1[4];
#pragma unroll
        for (int j = 0; j < 4; j++) {
            bool q0 = (e + j) < d0;
            bool q1 = (e + j) < d1;
            int s0 = q0 ? __ldg(es + b0 + e + j) : 0;
            int s1 = q1 ? __ldg(es + b1 + e + j) : 0;
            v0[j] = q0 ? __ldg(reinterpret_cast<const float2*>(x + (size_t)s0 * 64) + lane)
                       : make_float2(0.f, 0.f);
            v1[j] = q1 ? __ldg(reinterpret_cast<const float2*>(x + (size_t)s1 * 64) + lane)
                       : make_float2(0.f, 0.f);
        }
#pragma unroll
        for (int j = 0; j < 4; j++) {
            a0.x += v0[j].x; a0.y += v0[j].y;
            a1.x += v1[j].x; a1.y += v1[j].y;
        }
    }
    float i0 = 1.0f / fmaxf((float)d0, 1.0f);
    float i1 = 1.0f / fmaxf((float)d1, 1.0f);
    o0 = make_float2(a0.x * i0, a0.y * i0);
    o1 = make_float2(a1.x * i1, a1.y * i1);
}

// ---------------- layer-1 gather (standalone, high occupancy) ----------------
// One warp per (relation, node-pair). Warps [0,wd): rel0 from xd -> agg0.
// [wd, wd+wp): rel1 from xd -> agg1. [wd+wp, wd+2wp): rel2 from xp -> agg2.

__global__ void __launch_bounds__(256)
k_gather1(const float* __restrict__ xd, const float* __restrict__ xp,
          float* __restrict__ agg0, float* __restrict__ agg1,
          float* __restrict__ agg2, int nd, int np, int wd, int wp) {
    int gw = blockIdx.x * 8 + (threadIdx.x >> 5);
    int lane = threadIdx.x & 31;
    int rel, node0, n;
    const float* x;
    float* agg;
    if (gw < wd)            { rel = 0; node0 = gw * 2;              n = nd; x = xd; agg = agg0; }
    else if (gw < wd + wp)  { rel = 1; node0 = (gw - wd) * 2;       n = np; x = xd; agg = agg1; }
    else if (gw < wd + 2*wp){ rel = 2; node0 = (gw - wd - wp) * 2;  n = np; x = xp; agg = agg2; }
    else return;
    int node1 = node0 + 1;
    int b0, d0, b1, d1;
    node_range(g_rowfin[rel], node0, n, b0, d0);
    node_range(g_rowfin[rel], node1, n, b1, d1);
    float4 m0, m1;
    gpair128(g_esrc[rel], x, b0, d0, b1, d1, lane, m0, m1);
    if (node0 < n)
        *(reinterpret_cast<float4*>(agg + (size_t)node0 * 128) + lane) = m0;
    if (node1 < n)
        *(reinterpret_cast<float4*>(agg + (size_t)node1 * 128) + lane) = m1;
}

// ---------------- layer-1 GEMM (standalone; 4 rows x 2 cols per thread) ----------------
// 256 threads, 16 rows/block. Blocks [0,nbd): drug (agg0 -> h_d).
// [nbd,..): prot (agg1+agg2 dual -> h_p).

__global__ void __launch_bounds__(256)
k_gemm1(const float* __restrict__ agg0, const float* __restrict__ agg1,
        const float* __restrict__ agg2,
        const float* __restrict__ b1_ddi, const float* __restrict__ b1_dpi,
        const float* __restrict__ b1_ppi,
        float* __restrict__ h_d, float* __restrict__ h_p,
        int nd, int np, int nbd) {
    __shared__ __align__(16) float2 xs1[16][64];
    __shared__ __align__(16) float2 xs2[16][64];
    int tid = threadIdx.x;
    bool drug = (int)blockIdx.x < nbd;
    int row0 = (drug ? blockIdx.x : blockIdx.x - nbd) * 16;
    int n = drug ? nd : np;

    // stage 16 rows (k-paired float2, coalesced): 1024 float2 / 256 thr = 4 iters
#pragma unroll
    for (int it = 0; it < 4; it++) {
        int idx = tid + it * 256;
        int r = idx >> 6, k2 = idx & 63;
        int rr = row0 + r;
        if (drug) {
            xs1[r][k2] = (rr < n) ? *reinterpret_cast<const float2*>(agg0 + (size_t)rr * 128 + 2 * k2)
                                  : make_float2(0.f, 0.f);
        } else {
            xs1[r][k2] = (rr < n) ? *reinterpret_cast<const float2*>(agg1 + (size_t)rr * 128 + 2 * k2)
                                  : make_float2(0.f, 0.f);
            xs2[r][k2] = (rr < n) ? *reinterpret_cast<const float2*>(agg2 + (size_t)rr * 128 + 2 * k2)
                                  : make_float2(0.f, 0.f);
        }
    }
    __syncthreads();

    int j2 = tid & 63;
    int q  = tid >> 6;
    int rbase = q * 4;
    ull acc[4][2];
#pragma unroll
    for (int r = 0; r < 4; r++) { acc[r][0] = 0ull; acc[r][1] = 0ull; }

    if (drug) {
        const ull* w = reinterpret_cast<const ull*>(&g_w1i[0][0][0]);
        for (int i = 0; i < 32; i++) {
            ulonglong2 wA = *reinterpret_cast<const ulonglong2*>(w + (2 * i) * 128 + 2 * j2);
            ulonglong2 wB = *reinterpret_cast<const ulonglong2*>(w + (2 * i + 1) * 128 + 2 * j2);
#pragma unroll
            for (int r = 0; r < 4; r++) {
                ulonglong2 X = *reinterpret_cast<const ulonglong2*>(&xs1[rbase + r][2 * i]);
                acc[r][0] = ffma2(X.x, wA.x, acc[r][0]);
                acc[r][1] = ffma2(X.x, wA.y, acc[r][1]);
                acc[r][0] = ffma2(X.y, wB.x, acc[r][0]);
                acc[r][1] = ffma2(X.y, wB.y, acc[r][1]);
            }
        }
        float2 bb = __ldg(reinterpret_cast<const float2*>(b1_ddi) + j2);
#pragma unroll
        for (int r = 0; r < 4; r++) {
            float lo0, hi0, lo1, hi1;
            unpack2(acc[r][0], lo0, hi0);
            unpack2(acc[r][1], lo1, hi1);
            int rr = row0 + rbase + r;
            if (rr < n)
                *reinterpret_cast<float2*>(h_d + (size_t)rr * 128 + 2 * j2) =
                    make_float2(lo0 + hi0 + bb.x, lo1 + hi1 + bb.y);
        }
    } else {
        const ull* w1 = reinterpret_cast<const ull*>(&g_w1i[1][0][0]);
        const ull* w2 = reinterpret_cast<const ull*>(&g_w1i[2][0][0]);
        for (int i = 0; i < 32; i++) {
            ulonglong2 wA1 = *reinterpret_cast<const ulonglong2*>(w1 + (2 * i) * 128 + 2 * j2);
            ulonglong2 wB1 = *reinterpret_cast<const ulonglong2*>(w1 + (2 * i + 1) * 128 + 2 * j2);
            ulonglong2 wA2 = *reinterpret_cast<const ulonglong2*>(w2 + (2 * i) * 128 + 2 * j2);
            ulonglong2 wB2 = *reinterpret_cast<const ulonglong2*>(w2 + (2 * i + 1) * 128 + 2 * j2);
#pragma unroll
            for (int r = 0; r < 4; r++) {
                ulonglong2 X1 = *reinterpret_cast<const ulonglong2*>(&xs1[rbase + r][2 * i]);
                ulonglong2 X2 = *reinterpret_cast<const ulonglong2*>(&xs2[rbase + r][2 * i]);
                acc[r][0] = ffma2(X1.x, wA1.x, acc[r][0]);
                acc[r][1] = ffma2(X1.x, wA1.y, acc[r][1]);
                acc[r][0] = ffma2(X1.y, wB1.x, acc[r][0]);
                acc[r][1] = ffma2(X1.y, wB1.y, acc[r][1]);
                acc[r][0] = ffma2(X2.x, wA2.x, acc[r][0]);
                acc[r][1] = ffma2(X2.x, wA2.y, acc[r][1]);
                acc[r][0] = ffma2(X2.y, wB2.x, acc[r][0]);
                acc[r][1] = ffma2(X2.y, wB2.y, acc[r][1]);
            }
        }
        float2 ba = __ldg(reinterpret_cast<const float2*>(b1_dpi) + j2);
        float2 bc = __ldg(reinterpret_cast<const float2*>(b1_ppi) + j2);
        float bx = ba.x + bc.x, by = ba.y + bc.y;
#pragma unroll
        for (int r = 0; r < 4; r++) {
            float lo0, hi0, lo1, hi1;
            unpack2(acc[r][0], lo0, hi0);
            unpack2(acc[r][1], lo1, hi1);
            int rr = row0 + rbase + r;
            if (rr < n)
                *reinterpret_cast<float2*>(h_p + (size_t)rr * 128 + 2 * j2) =
                    make_float2(lo0 + hi0 + bx, lo1 + hi1 + by);
        }
    }
}

// ---------------- layer-2 GEMM (round-12: 4 rows x 2 cols per thread) ----------------

__global__ void __launch_bounds__(128)
k_gemm2(const float* __restrict__ h_d, const float* __restrict__ h_p,
        float* __restrict__ t_ddi, float* __restrict__ t_dpi,
        float* __restrict__ t_ppi, int nd, int np, int nbA) {
    __shared__ __align__(16) float2 xs[16][64];
    int tid = threadIdx.x;
    int bt = ((int)blockIdx.x < nbA) ? 0 : (((int)blockIdx.x < 2 * nbA) ? 1 : 2);
    int row0, n, rel;
    const float* H;
    float* T;
    if (bt == 0)      { row0 = blockIdx.x * 16;             n = nd; H = h_d; T = t_ddi; rel = 0; }
    else if (bt == 1) { row0 = (blockIdx.x - nbA) * 16;     n = nd; H = h_d; T = t_dpi; rel = 1; }
    else              { row0 = (blockIdx.x - 2 * nbA) * 16; n = np; H = h_p; T = t_ppi; rel = 2; }

#pragma unroll
    for (int it = 0; it < 8; it++) {
        int idx = tid + it * 128;
        int r = idx >> 6, k2 = idx & 63;
        int rr = row0 + r;
        xs[r][k2] = (rr < n) ? *reinterpret_cast<const float2*>(H + (size_t)rr * 128 + 2 * k2)
                             : make_float2(0.f, 0.f);
    }
    __syncthreads();

    int c2 = tid & 31;
    int rbase = (tid >> 5) * 4;
    const ull* w = reinterpret_cast<const ull*>(&g_w2i[rel][0][0]);
    ull acc[4][2];
#pragma unroll
    for (int r = 0; r < 4; r++) { acc[r][0] = 0ull; acc[r][1] = 0ull; }
    for (int i = 0; i < 32; i++) {
        ulonglong2 wA = *reinterpret_cast<const ulonglong2*>(w + (2 * i) * 64 + 2 * c2);
        ulonglong2 wB = *reinterpret_cast<const ulonglong2*>(w + (2 * i + 1) * 64 + 2 * c2);
#pragma unroll
        for (int r = 0; r < 4; r++) {
            ulonglong2 X = *reinterpret_cast<const ulonglong2*>(&xs[rbase + r][2 * i]);
            acc[r][0] = ffma2(X.x, wA.x, acc[r][0]);
            acc[r][1] = ffma2(X.x, wA.y, acc[r][1]);
            acc[r][0] = ffma2(X.y, wB.x, acc[r][0]);
            acc[r][1] = ffma2(X.y, wB.y, acc[r][1]);
        }
    }
#pragma unroll
    for (int r = 0; r < 4; r++) {
        float lo0, hi0, lo1, hi1;
        unpack2(acc[r][0], lo0, hi0);
        unpack2(acc[r][1], lo1, hi1);
        int rr = row0 + rbase + r;
        if (rr < n)
            *reinterpret_cast<float2*>(T + (size_t)rr * 64 + 2 * c2) =
                make_float2(lo0 + hi0, lo1 + hi1);
    }
}

// ---------------- layer-2 gather + bias + concat + end-zeroing ----------------

__global__ void __launch_bounds__(256)
k_out(const float* __restrict__ t_ddi, const float* __restrict__ t_dpi,
      const float* __restrict__ t_ppi,
      const float* __restrict__ b2_ddi, const float* __restrict__ b2_dpi,
      const float* __restrict__ b2_ppi,
      float* __restrict__ out, int nd, int np, int wd, int nb_main) {
    if ((int)blockIdx.x >= nb_main) {
        int zt = (blockIdx.x - nb_main) * 256 + threadIdx.x;
        int stride = ZERO_BLKS * 256;
        int* p = &g_cnt[0][0];
        for (int i = zt; i < 3 * (NMAX + 1); i += stride) p[i] = 0;
        return;
    }
    int gw = blockIdx.x * 8 + (threadIdx.x >> 5);
    int lane = threadIdx.x & 31;
    if (gw < wd) {
        int node0 = gw * 2, node1 = node0 + 1;
        int b0, d0, b1, d1;
        node_range(g_rowfin[0], node0, nd, b0, d0);
        node_range(g_rowfin[0], node1, nd, b1, d1);
        float2 m0, m1;
        gpair64(g_esrc[0], t_ddi, b0, d0, b1, d1, lane, m0, m1);
        float2 bb = __ldg(reinterpret_cast<const float2*>(b2_ddi) + lane);
        if (node0 < nd)
            *(reinterpret_cast<float2*>(out + (size_t)node0 * 64) + lane) =
                make_float2(m0.x + bb.x, m0.y + bb.y);
        if (node1 < nd)
            *(reinterpret_cast<float2*>(out + (size_t)node1 * 64) + lane) =
                make_float2(m1.x + bb.x, m1.y + bb.y);
    } else {
        int node0 = (gw - wd) * 2, node1 = node0 + 1;
        int b0, d0, b1, d1;
        node_range(g_rowfin[1], node0, np, b0, d0);
        node_range(g_rowfin[1], node1, np, b1, d1);
        float2 ma0, ma1;
        gpair64(g_esrc[1], t_dpi, b0, d0, b1, d1, lane, ma0, ma1);
        node_range(g_rowfin[2], node0, np, b0, d0);
        node_range(g_rowfin[2], node1, np, b1, d1);
        float2 mb0, mb1;
        gpair64(g_esrc[2], t_ppi, b0, d0, b1, d1, lane, mb0, mb1);
        float2 ba = __ldg(reinterpret_cast<const float2*>(b2_dpi) + lane);
        float2 bc = __ldg(reinterpret_cast<const float2*>(b2_ppi) + lane);
        float bx = ba.x + bc.x, by = ba.y + bc.y;
        if (node0 < np)
            *(reinterpret_cast<float2*>(out + (size_t)(nd + node0) * 64) + lane) =
                make_float2(ma0.x + mb0.x + bx, ma0.y + mb0.y + by);
        if (node1 < np)
            *(reinterpret_cast<float2*>(out + (size_t)(nd + node1) * 64) + lane) =
                make_float2(ma1.x + mb1.x + bx, ma1.y + mb1.y + by);
    }
}

// ---------------- host launcher ----------------

static float* fs_ptr() {
    static float* p = nullptr;
    if (!p) cudaGetSymbolAddress((void**)&p, g_fs);
    return p;
}

static inline int cdiv(long long a, long long b) { return (int)((a + b - 1) / b); }

extern "C" void kernel_launch(void* const* d_in, const int* in_sizes, int n_in,
                              void* d_out, int out_size) {
    const float* x_drug = (const float*)d_in[0];
    const float* x_prot = (const float*)d_in[1];
    const int* src_ddi = (const int*)d_in[2];
    const int* dst_ddi = (const int*)d_in[3];
    const int* src_dpi = (const int*)d_in[4];
    const int* dst_dpi = (const int*)d_in[5];
    const int* src_ppi = (const int*)d_in[6];
    const int* dst_ppi = (const int*)d_in[7];
    const float* W1_ddi = (const float*)d_in[8];
    const float* b1_ddi = (const float*)d_in[9];
    const float* W1_dpi = (const float*)d_in[10];
    const float* b1_dpi = (const float*)d_in[11];
    const float* W1_ppi = (const float*)d_in[12];
    const float* b1_ppi = (const float*)d_in[13];
    const float* W2_ddi = (const float*)d_in[14];
    const float* b2_ddi = (const float*)d_in[15];
    const float* W2_dpi = (const float*)d_in[16];
    const float* b2_dpi = (const float*)d_in[17];
    const float* W2_ppi = (const float*)d_in[18];
    const float* b2_ppi = (const float*)d_in[19];
    float* out = (float*)d_out;

    int nd = in_sizes[0] / 128;
    int np = in_sizes[1] / 128;
    int ed = in_sizes[2];
    int ep = in_sizes[4];
    int eq = in_sizes[6];

    float* S = fs_ptr();
    float* agg0  = S + F_AGG0;
    float* agg1  = S + F_AGG1;
    float* agg2  = S + F_AGG2;
    float* h_d   = S + F_HD;
    float* h_p   = S + F_HP;
    float* t_ddi = S + F_T_DDI;
    float* t_dpi = S + F_T_DPI;
    float* t_ppi = S + F_T_PPI;

    int emax = ed > ep ? ed : ep;
    if (eq > emax) emax = eq;
    int nmax = nd > np ? nd : np;
    int sblk = cdiv(nmax, SCAN_BLK);

    // ---- CSR build + W interleave: 3 launches ----
    int nb_count = cdiv(emax, 256);
    k_count<<<nb_count + WPREP_BLKS, 256>>>(dst_ddi, ed, dst_dpi, ep, dst_ppi, eq,
                                            W1_ddi, W1_dpi, W1_ppi,
                                            W2_ddi, W2_dpi, W2_ppi, nb_count);
    k_scan12<<<3 * sblk, 1024>>>(sblk, nd, np, np);
    k_fillfin<<<cdiv(emax, 256), 256>>>(src_ddi, dst_ddi, ed,
                                        src_dpi, dst_dpi, ep,
                                        src_ppi, dst_ppi, eq, nd, np, np);

    // ---- layer 1: standalone gather (launch index 3 -> profiled) ----
    int wd1 = cdiv(nd, 2), wp1 = cdiv(np, 2);
    k_gather1<<<cdiv(wd1 + 2 * wp1, 8), 256>>>(x_drug, x_prot, agg0, agg1, agg2,
                                               nd, np, wd1, wp1);

    // ---- layer 1 GEMM ----
    int nbd1 = cdiv(nd, 16), nbp1 = cdiv(np, 16);
    k_gemm1<<<nbd1 + nbp1, 256>>>(agg0, agg1, agg2, b1_ddi, b1_dpi, b1_ppi,
                                  h_d, h_p, nd, np, nbd1);

    // ---- layer 2 transforms ----
    int nbA = cdiv(nd, 16), nbC = cdiv(np, 16);
    k_gemm2<<<2 * nbA + nbC, 128>>>(h_d, h_p, t_ddi, t_dpi, t_ppi, nd, np, nbA);

    // ---- layer 2 gather + bias + concat (+ zero g_cnt for next replay) ----
    int wd = cdiv(nd, 2), wp = cdiv(np, 2);
    int nb_main = cdiv(wd + wp, 8);
    k_out<<<nb_main + ZERO_BLKS, 256>>>(t_ddi, t_dpi, t_ppi,
                                        b2_ddi, b2_dpi, b2_ppi, out, nd, np, wd, nb_main);
}

// round 16
// speedup vs baseline: 1.1588x; 1.1588x over previous
#include <cuda_runtime.h>
#include <stdint.h>

#define NMAX 50000
#define EMAX 600000
#define SCAN_BLK 2048
#define MAX_SBLK 32
#define ZERO_BLKS 64
#define WPREP_BLKS 144   // 3*64*128 + 3*64*64 = 36864 elems / 256

typedef unsigned long long ull;

// ---------------- CSR scratch ----------------
__device__ int g_cnt[3][NMAX + 1];
__device__ int g_rowfin[3][NMAX + 1];
__device__ int g_rank[3][EMAX];
__device__ int g_esrc[3][EMAX];
__device__ int g_bsum[3][MAX_SBLK];
__device__ int g_boff[3][MAX_SBLK];
__device__ int g_total[3];
__device__ int g_arrive[3];

// ---------------- interleaved weights ----------------
__device__ __align__(16) float2 g_w1i[3][64][128];   // (W1[2kk][j], W1[2kk+1][j])
__device__ __align__(16) float2 g_w2i[3][64][64];    // (W2[2kk][c], W2[2kk+1][c])

// ---------------- float scratch ----------------
constexpr size_t F_HD    = 0;
constexpr size_t F_HP    = F_HD    + (size_t)NMAX * 128;
constexpr size_t F_T_DDI = F_HP    + (size_t)NMAX * 128;
constexpr size_t F_T_DPI = F_T_DDI + (size_t)NMAX * 64;
constexpr size_t F_T_PPI = F_T_DPI + (size_t)NMAX * 64;
constexpr size_t F_TOTAL = F_T_PPI + (size_t)NMAX * 64;
__device__ float g_fs[F_TOTAL];

// ---------------- packed f32x2 helpers ----------------
__device__ __forceinline__ ull ffma2(ull a, ull b, ull c) {
    ull d;
    asm("fma.rn.f32x2 %0, %1, %2, %3;" : "=l"(d) : "l"(a), "l"(b), "l"(c));
    return d;
}
__device__ __forceinline__ void unpack2(ull v, float& lo, float& hi) {
    asm("mov.b64 {%0, %1}, %2;" : "=f"(lo), "=f"(hi) : "l"(v));
}

// ---------------- CSR build + W interleave (launch 0) ----------------

__global__ void k_count(const int* __restrict__ d0, int e0,
                        const int* __restrict__ d1, int e1,
                        const int* __restrict__ d2, int e2,
                        const float* __restrict__ W1_ddi, const float* __restrict__ W1_dpi,
                        const float* __restrict__ W1_ppi,
                        const float* __restrict__ W2_ddi, const float* __restrict__ W2_dpi,
                        const float* __restrict__ W2_ppi,
                        int nb_count) {
    if ((int)blockIdx.x >= nb_count) {
        int t = (blockIdx.x - nb_count) * 256 + threadIdx.x;
        int n1 = 3 * 64 * 128;
        if (t < n1) {
            int rel = t / (64 * 128);
            int rem = t % (64 * 128);
            int kk = rem >> 7, j = rem & 127;
            const float* W = (rel == 0) ? W1_ddi : ((rel == 1) ? W1_dpi : W1_ppi);
            g_w1i[rel][kk][j] = make_float2(__ldg(W + (2 * kk) * 128 + j),
                                            __ldg(W + (2 * kk + 1) * 128 + j));
        } else if (t < n1 + 3 * 64 * 64) {
            int u = t - n1;
            int rel = u / (64 * 64);
            int rem = u % (64 * 64);
            int kk = rem >> 6, c = rem & 63;
            const float* W = (rel == 0) ? W2_ddi : ((rel == 1) ? W2_dpi : W2_ppi);
            g_w2i[rel][kk][c] = make_float2(__ldg(W + (2 * kk) * 64 + c),
                                            __ldg(W + (2 * kk + 1) * 64 + c));
        }
        return;
    }
    int i = blockIdx.x * 256 + threadIdx.x;
    int stride = nb_count * 256;
    for (int j = i; j < e0; j += stride)
        g_rank[0][j] = atomicAdd(&g_cnt[0][__ldg(d0 + j)], 1);
    for (int j = i; j < e1; j += stride)
        g_rank[1][j] = atomicAdd(&g_cnt[1][__ldg(d1 + j)], 1);
    for (int j = i; j < e2; j += stride)
        g_rank[2][j] = atomicAdd(&g_cnt[2][__ldg(d2 + j)], 1);
}

__global__ void __launch_bounds__(1024)
k_scan12(int sblk, int n0, int n1, int n2) {
    __shared__ int sh[1024];
    __shared__ bool is_last;
    int rel = blockIdx.x / sblk;
    int blk = blockIdx.x % sblk;
    int n = (rel == 0) ? n0 : ((rel == 1) ? n1 : n2);
    int* cnt = g_cnt[rel];
    int tid = threadIdx.x;
    int base = blk * SCAN_BLK + tid * 2;
    int c0 = (base < n)     ? cnt[base]     : 0;
    int c1 = (base + 1 < n) ? cnt[base + 1] : 0;
    sh[tid] = c0 + c1;
    __syncthreads();
    for (int off = 1; off < 1024; off <<= 1) {
        int v = (tid >= off) ? sh[tid - off] : 0;
        __syncthreads();
        sh[tid] += v;
        __syncthreads();
    }
    int toff = (tid > 0) ? sh[tid - 1] : 0;
    if (base < n)     cnt[base]     = toff;
    if (base + 1 < n) cnt[base + 1] = toff + c0;
    if (tid == 1023) g_bsum[rel][blk] = sh[1023];

    __threadfence();
    __syncthreads();
    if (tid == 0) {
        int old = atomicAdd(&g_arrive[rel], 1);
        is_last = (old == sblk - 1);
    }
    __syncthreads();
    if (is_last && tid < 32) {
        int v = (tid < sblk) ? g_bsum[rel][tid] : 0;
        int orig = v;
#pragma unroll
        for (int off = 1; off < 32; off <<= 1) {
            int u = __shfl_up_sync(0xFFFFFFFF, v, off);
            if (tid >= off) v += u;
        }
        if (tid < sblk) g_boff[rel][tid] = v - orig;
        if (tid == 31) {
            g_total[rel] = v;
            g_arrive[rel] = 0;
        }
    }
}

__global__ void k_fillfin(const int* __restrict__ s0, const int* __restrict__ d0, int e0,
                          const int* __restrict__ s1, const int* __restrict__ d1, int e1,
                          const int* __restrict__ s2, const int* __restrict__ d2, int e2,
                          int n0, int n1, int n2) {
    int i = blockIdx.x * blockDim.x + threadIdx.x;
    int stride = gridDim.x * blockDim.x;
    for (int e = i; e < e0; e += stride) {
        int d = __ldg(d0 + e);
        int pos = g_cnt[0][d] + g_boff[0][d >> 11] + g_rank[0][e];
        g_esrc[0][pos] = __ldg(s0 + e);
    }
    for (int e = i; e < e1; e += stride) {
        int d = __ldg(d1 + e);
        int pos = g_cnt[1][d] + g_boff[1][d >> 11] + g_rank[1][e];
        g_esrc[1][pos] = __ldg(s1 + e);
    }
    for (int e = i; e < e2; e += stride) {
        int d = __ldg(d2 + e);
        int pos = g_cnt[2][d] + g_boff[2][d >> 11] + g_rank[2][e];
        g_esrc[2][pos] = __ldg(s2 + e);
    }
    int totalf = 3 * (NMAX + 1);
    for (int t = i; t < totalf; t += stride) {
        int rel = t / (NMAX + 1);
        int idx = t % (NMAX + 1);
        int n = (rel == 0) ? n0 : ((rel == 1) ? n1 : n2);
        if (idx < n)
            g_rowfin[rel][idx] = g_cnt[rel][idx] + g_boff[rel][idx >> 11];
        else if (idx == n)
            g_rowfin[rel][n] = g_total[rel];
    }
}

// ---------------- gather primitives ----------------

__device__ __forceinline__ void node_range(const int* __restrict__ ptr, int node, int n,
                                           int& b, int& d) {
    if (node < n) {
        b = ptr[node];
        d = ptr[node + 1] - b;
    } else {
        b = 0; d = 0;
    }
}

__device__ __forceinline__ void gpair128(const int* __restrict__ es,
                                         const float* __restrict__ x,
                                         int b0, int d0, int b1, int d1, int lane,
                                         float4& o0, float4& o1) {
    float4 a0 = make_float4(0.f, 0.f, 0.f, 0.f);
    float4 a1 = make_float4(0.f, 0.f, 0.f, 0.f);
    int m = d0 > d1 ? d0 : d1;
    for (int e = 0; e < m; e += 4) {
        float4 v0[4], v1[4];
#pragma unroll
        for (int j = 0; j < 4; j++) {
            bool q0 = (e + j) < d0;
            bool q1 = (e + j) < d1;
            int s0 = q0 ? __ldg(es + b0 + e + j) : 0;
            int s1 = q1 ? __ldg(es + b1 + e + j) : 0;
            v0[j] = q0 ? __ldg(reinterpret_cast<const float4*>(x + (size_t)s0 * 128) + lane)
                       : make_float4(0.f, 0.f, 0.f, 0.f);
            v1[j] = q1 ? __ldg(reinterpret_cast<const float4*>(x + (size_t)s1 * 128) + lane)
                       : make_float4(0.f, 0.f, 0.f, 0.f);
        }
#pragma unroll
        for (int j = 0; j < 4; j++) {
            a0.x += v0[j].x; a0.y += v0[j].y; a0.z += v0[j].z; a0.w += v0[j].w;
            a1.x += v1[j].x; a1.y += v1[j].y; a1.z += v1[j].z; a1.w += v1[j].w;
        }
    }
    float i0 = 1.0f / fmaxf((float)d0, 1.0f);
    float i1 = 1.0f / fmaxf((float)d1, 1.0f);
    o0 = make_float4(a0.x * i0, a0.y * i0, a0.z * i0, a0.w * i0);
    o1 = make_float4(a1.x * i1, a1.y * i1, a1.z * i1, a1.w * i1);
}

__device__ __forceinline__ void gpair64(const int* __restrict__ es,
                                        const float* __restrict__ x,
                                        int b0, int d0, int b1, int d1, int lane,
                                        float2& o0, float2& o1) {
    float2 a0 = make_float2(0.f, 0.f);
    float2 a1 = make_float2(0.f, 0.f);
    int m = d0 > d1 ? d0 : d1;
    for (int e = 0; e < m; e += 4) {
        float2 v0[4], v1[4];
#pragma unroll
        for (int j = 0; j < 4; j++) {
            bool q0 = (e + j) < d0;
            bool q1 = (e + j) < d1;
            int s0 = q0 ? __ldg(es + b0 + e + j) : 0;
            int s1 = q1 ? __ldg(es + b1 + e + j) : 0;
            v0[j] = q0 ? __ldg(reinterpret_cast<const float2*>(x + (size_t)s0 * 64) + lane)
                       : make_float2(0.f, 0.f);
            v1[j] = q1 ? __ldg(reinterpret_cast<const float2*>(x + (size_t)s1 * 64) + lane)
                       : make_float2(0.f, 0.f);
        }
#pragma unroll
        for (int j = 0; j < 4; j++) {
            a0.x += v0[j].x; a0.y += v0[j].y;
            a1.x += v1[j].x; a1.y += v1[j].y;
        }
    }
    float i0 = 1.0f / fmaxf((float)d0, 1.0f);
    float i1 = 1.0f / fmaxf((float)d1, 1.0f);
    o0 = make_float2(a0.x * i0, a0.y * i0);
    o1 = make_float2(a1.x * i1, a1.y * i1);
}

// ---------------- fused layer-1 (round-12: 4 rows x 2 cols per thread) ----------------

__global__ void __launch_bounds__(256, 3)
k_l1(const float* __restrict__ xd, const float* __restrict__ xp,
     const float* __restrict__ b1_ddi, const float* __restrict__ b1_dpi,
     const float* __restrict__ b1_ppi,
     float* __restrict__ h_d, float* __restrict__ h_p,
     int nd, int np, int nbd) {
    __shared__ __align__(16) float2 xs1[16][64];
    __shared__ __align__(16) float2 xs2[16][64];
    int tid = threadIdx.x, wid = tid >> 5, lane = tid & 31;
    bool drug = (int)blockIdx.x < nbd;
    int row0 = (drug ? blockIdx.x : blockIdx.x - nbd) * 16;
    int n = drug ? nd : np;

    int r0 = wid * 2, r1 = r0 + 1;
    int node0 = row0 + r0, node1 = row0 + r1;

    if (drug) {
        int b0, d0, b1, d1;
        node_range(g_rowfin[0], node0, n, b0, d0);
        node_range(g_rowfin[0], node1, n, b1, d1);
        float4 m0, m1;
        gpair128(g_esrc[0], xd, b0, d0, b1, d1, lane, m0, m1);
        xs1[r0][2 * lane]     = make_float2(m0.x, m0.y);
        xs1[r0][2 * lane + 1] = make_float2(m0.z, m0.w);
        xs1[r1][2 * lane]     = make_float2(m1.x, m1.y);
        xs1[r1][2 * lane + 1] = make_float2(m1.z, m1.w);
    } else {
        int b0, d0, b1, d1;
        node_range(g_rowfin[1], node0, n, b0, d0);
        node_range(g_rowfin[1], node1, n, b1, d1);
        float4 m0, m1;
        gpair128(g_esrc[1], xd, b0, d0, b1, d1, lane, m0, m1);
        xs1[r0][2 * lane]     = make_float2(m0.x, m0.y);
        xs1[r0][2 * lane + 1] = make_float2(m0.z, m0.w);
        xs1[r1][2 * lane]     = make_float2(m1.x, m1.y);
        xs1[r1][2 * lane + 1] = make_float2(m1.z, m1.w);

        node_range(g_rowfin[2], node0, n, b0, d0);
        node_range(g_rowfin[2], node1, n, b1, d1);
        gpair128(g_esrc[2], xp, b0, d0, b1, d1, lane, m0, m1);
        xs2[r0][2 * lane]     = make_float2(m0.x, m0.y);
        xs2[r0][2 * lane + 1] = make_float2(m0.z, m0.w);
        xs2[r1][2 * lane]     = make_float2(m1.x, m1.y);
        xs2[r1][2 * lane + 1] = make_float2(m1.z, m1.w);
    }
    __syncthreads();

    // GEMM phase: thread = (j2, q): columns 2j2, 2j2+1; rows q*4 .. q*4+3.
    int j2 = tid & 63;
    int q  = tid >> 6;
    int rbase = q * 4;
    ull acc[4][2];
#pragma unroll
    for (int r = 0; r < 4; r++) { acc[r][0] = 0ull; acc[r][1] = 0ull; }

    if (drug) {
        const ull* w = reinterpret_cast<const ull*>(&g_w1i[0][0][0]);
        for (int i = 0; i < 32; i++) {
            ulonglong2 wA = *reinterpret_cast<const ulonglong2*>(w + (2 * i) * 128 + 2 * j2);
            ulonglong2 wB = *reinterpret_cast<const ulonglong2*>(w + (2 * i + 1) * 128 + 2 * j2);
#pragma unroll
            for (int r = 0; r < 4; r++) {
                ulonglong2 X = *reinterpret_cast<const ulonglong2*>(&xs1[rbase + r][2 * i]);
                acc[r][0] = ffma2(X.x, wA.x, acc[r][0]);
                acc[r][1] = ffma2(X.x, wA.y, acc[r][1]);
                acc[r][0] = ffma2(X.y, wB.x, acc[r][0]);
                acc[r][1] = ffma2(X.y, wB.y, acc[r][1]);
            }
        }
        float2 bb = __ldg(reinterpret_cast<const float2*>(b1_ddi) + j2);
#pragma unroll
        for (int r = 0; r < 4; r++) {
            float lo0, hi0, lo1, hi1;
            unpack2(acc[r][0], lo0, hi0);
            unpack2(acc[r][1], lo1, hi1);
            int rr = row0 + rbase + r;
            if (rr < n)
                *reinterpret_cast<float2*>(h_d + (size_t)rr * 128 + 2 * j2) =
                    make_float2(lo0 + hi0 + bb.x, lo1 + hi1 + bb.y);
        }
    } else {
        const ull* w1 = reinterpret_cast<const ull*>(&g_w1i[1][0][0]);
        const ull* w2 = reinterpret_cast<const ull*>(&g_w1i[2][0][0]);
        for (int i = 0; i < 32; i++) {
            ulonglong2 wA1 = *reinterpret_cast<const ulonglong2*>(w1 + (2 * i) * 128 + 2 * j2);
            ulonglong2 wB1 = *reinterpret_cast<const ulonglong2*>(w1 + (2 * i + 1) * 128 + 2 * j2);
            ulonglong2 wA2 = *reinterpret_cast<const ulonglong2*>(w2 + (2 * i) * 128 + 2 * j2);
            ulonglong2 wB2 = *reinterpret_cast<const ulonglong2*>(w2 + (2 * i + 1) * 128 + 2 * j2);
#pragma unroll
            for (int r = 0; r < 4; r++) {
                ulonglong2 X1 = *reinterpret_cast<const ulonglong2*>(&xs1[rbase + r][2 * i]);
                ulonglong2 X2 = *reinterpret_cast<const ulonglong2*>(&xs2[rbase + r][2 * i]);
                acc[r][0] = ffma2(X1.x, wA1.x, acc[r][0]);
                acc[r][1] = ffma2(X1.x, wA1.y, acc[r][1]);
                acc[r][0] = ffma2(X1.y, wB1.x, acc[r][0]);
                acc[r][1] = ffma2(X1.y, wB1.y, acc[r][1]);
                acc[r][0] = ffma2(X2.x, wA2.x, acc[r][0]);
                acc[r][1] = ffma2(X2.x, wA2.y, acc[r][1]);
                acc[r][0] = ffma2(X2.y, wB2.x, acc[r][0]);
                acc[r][1] = ffma2(X2.y, wB2.y, acc[r][1]);
            }
        }
        float2 ba = __ldg(reinterpret_cast<const float2*>(b1_dpi) + j2);
        float2 bc = __ldg(reinterpret_cast<const float2*>(b1_ppi) + j2);
        float bx = ba.x + bc.x, by = ba.y + bc.y;
#pragma unroll
        for (int r = 0; r < 4; r++) {
            float lo0, hi0, lo1, hi1;
            unpack2(acc[r][0], lo0, hi0);
            unpack2(acc[r][1], lo1, hi1);
            int rr = row0 + rbase + r;
            if (rr < n)
                *reinterpret_cast<float2*>(h_p + (size_t)rr * 128 + 2 * j2) =
                    make_float2(lo0 + hi0 + bx, lo1 + hi1 + by);
        }
    }
}

// ---------------- layer-2 GEMM: drug blocks dual-output (one h_d staging) ----------------
// 256 threads. Drug blocks [0, nbA): stage 16 rows of h_d once; threads <128
// compute t_ddi, threads >=128 compute t_dpi (4 rows x 2 cols per thread).
// Prot blocks [nbA, ..): 32 rows of h_p -> t_ppi (4 rows x 2 cols per thread).

__global__ void __launch_bounds__(256)
k_gemm2(const float* __restrict__ h_d, const float* __restrict__ h_p,
        float* __restrict__ t_ddi, float* __restrict__ t_dpi,
        float* __restrict__ t_ppi, int nd, int np, int nbA) {
    __shared__ __align__(16) float2 xs[32][64];
    int tid = threadIdx.x;
    bool drug = (int)blockIdx.x < nbA;

    if (drug) {
        int row0 = blockIdx.x * 16;
#pragma unroll
        for (int it = 0; it < 4; it++) {
            int idx = tid + it * 256;
            int r = idx >> 6, k2 = idx & 63;
            int rr = row0 + r;
            xs[r][k2] = (rr < nd) ? *reinterpret_cast<const float2*>(h_d + (size_t)rr * 128 + 2 * k2)
                                  : make_float2(0.f, 0.f);
        }
        __syncthreads();
        int half = tid >> 7;                 // 0 -> ddi, 1 -> dpi
        int c2 = tid & 31;
        int rbase = ((tid >> 5) & 3) * 4;
        const ull* w = reinterpret_cast<const ull*>(&g_w2i[half][0][0]);
        float* T = half ? t_dpi : t_ddi;
        ull acc[4][2];
#pragma unroll
        for (int r = 0; r < 4; r++) { acc[r][0] = 0ull; acc[r][1] = 0ull; }
        for (int i = 0; i < 32; i++) {
            ulonglong2 wA = *reinterpret_cast<const ulonglong2*>(w + (2 * i) * 64 + 2 * c2);
            ulonglong2 wB = *reinterpret_cast<const ulonglong2*>(w + (2 * i + 1) * 64 + 2 * c2);
#pragma unroll
            for (int r = 0; r < 4; r++) {
                ulonglong2 X = *reinterpret_cast<const ulonglong2*>(&xs[rbase + r][2 * i]);
                acc[r][0] = ffma2(X.x, wA.x, acc[r][0]);
                acc[r][1] = ffma2(X.x, wA.y, acc[r][1]);
                acc[r][0] = ffma2(X.y, wB.x, acc[r][0]);
                acc[r][1] = ffma2(X.y, wB.y, acc[r][1]);
            }
        }
#pragma unroll
        for (int r = 0; r < 4; r++) {
            float lo0, hi0, lo1, hi1;
            unpack2(acc[r][0], lo0, hi0);
            unpack2(acc[r][1], lo1, hi1);
            int rr = row0 + rbase + r;
            if (rr < nd)
                *reinterpret_cast<float2*>(T + (size_t)rr * 64 + 2 * c2) =
                    make_float2(lo0 + hi0, lo1 + hi1);
        }
    } else {
        int row0 = (blockIdx.x - nbA) * 32;
#pragma unroll
        for (int it = 0; it < 8; it++) {
            int idx = tid + it * 256;
            int r = idx >> 6, k2 = idx & 63;
            int rr = row0 + r;
            xs[r][k2] = (rr < np) ? *reinterpret_cast<const float2*>(h_p + (size_t)rr * 128 + 2 * k2)
                                  : make_float2(0.f, 0.f);
        }
        __syncthreads();
        int c2 = tid & 31;
        int rbase = (tid >> 5) * 4;          // 8 groups x 4 rows = 32 rows
        const ull* w = reinterpret_cast<const ull*>(&g_w2i[2][0][0]);
        ull acc[4][2];
#pragma unroll
        for (int r = 0; r < 4; r++) { acc[r][0] = 0ull; acc[r][1] = 0ull; }
        for (int i = 0; i < 32; i++) {
            ulonglong2 wA = *reinterpret_cast<const ulonglong2*>(w + (2 * i) * 64 + 2 * c2);
            ulonglong2 wB = *reinterpret_cast<const ulonglong2*>(w + (2 * i + 1) * 64 + 2 * c2);
#pragma unroll
            for (int r = 0; r < 4; r++) {
                ulonglong2 X = *reinterpret_cast<const ulonglong2*>(&xs[rbase + r][2 * i]);
                acc[r][0] = ffma2(X.x, wA.x, acc[r][0]);
                acc[r][1] = ffma2(X.x, wA.y, acc[r][1]);
                acc[r][0] = ffma2(X.y, wB.x, acc[r][0]);
                acc[r][1] = ffma2(X.y, wB.y, acc[r][1]);
            }
        }
#pragma unroll
        for (int r = 0; r < 4; r++) {
            float lo0, hi0, lo1, hi1;
            unpack2(acc[r][0], lo0, hi0);
            unpack2(acc[r][1], lo1, hi1);
            int rr = row0 + rbase + r;
            if (rr < np)
                *reinterpret_cast<float2*>(t_ppi + (size_t)rr * 64 + 2 * c2) =
                    make_float2(lo0 + hi0, lo1 + hi1);
        }
    }
}

// ---------------- layer-2 gather + bias + concat + end-zeroing ----------------

__global__ void __launch_bounds__(256)
k_out(const float* __restrict__ t_ddi, const float* __restrict__ t_dpi,
      const float* __restrict__ t_ppi,
      const float* __restrict__ b2_ddi, const float* __restrict__ b2_dpi,
      const float* __restrict__ b2_ppi,
      float* __restrict__ out, int nd, int np, int wd, int nb_main) {
    if ((int)blockIdx.x >= nb_main) {
        int zt = (blockIdx.x - nb_main) * 256 + threadIdx.x;
        int stride = ZERO_BLKS * 256;
        int* p = &g_cnt[0][0];
        for (int i = zt; i < 3 * (NMAX + 1); i += stride) p[i] = 0;
        return;
    }
    int gw = blockIdx.x * 8 + (threadIdx.x >> 5);
    int lane = threadIdx.x & 31;
    if (gw < wd) {
        int node0 = gw * 2, node1 = node0 + 1;
        int b0, d0, b1, d1;
        node_range(g_rowfin[0], node0, nd, b0, d0);
        node_range(g_rowfin[0], node1, nd, b1, d1);
        float2 m0, m1;
        gpair64(g_esrc[0], t_ddi, b0, d0, b1, d1, lane, m0, m1);
        float2 bb = __ldg(reinterpret_cast<const float2*>(b2_ddi) + lane);
        if (node0 < nd)
            *(reinterpret_cast<float2*>(out + (size_t)node0 * 64) + lane) =
                make_float2(m0.x + bb.x, m0.y + bb.y);
        if (node1 < nd)
            *(reinterpret_cast<float2*>(out + (size_t)node1 * 64) + lane) =
                make_float2(m1.x + bb.x, m1.y + bb.y);
    } else {
        int node0 = (gw - wd) * 2, node1 = node0 + 1;
        int b0, d0, b1, d1;
        node_range(g_rowfin[1], node0, np, b0, d0);
        node_range(g_rowfin[1], node1, np, b1, d1);
        float2 ma0, ma1;
        gpair64(g_esrc[1], t_dpi, b0, d0, b1, d1, lane, ma0, ma1);
        node_range(g_rowfin[2], node0, np, b0, d0);
        node_range(g_rowfin[2], node1, np, b1, d1);
        float2 mb0, mb1;
        gpair64(g_esrc[2], t_ppi, b0, d0, b1, d1, lane, mb0, mb1);
        float2 ba = __ldg(reinterpret_cast<const float2*>(b2_dpi) + lane);
        float2 bc = __ldg(reinterpret_cast<const float2*>(b2_ppi) + lane);
        float bx = ba.x + bc.x, by = ba.y + bc.y;
        if (node0 < np)
            *(reinterpret_cast<float2*>(out + (size_t)(nd + node0) * 64) + lane) =
                make_float2(ma0.x + mb0.x + bx, ma0.y + mb0.y + by);
        if (node1 < np)
            *(reinterpret_cast<float2*>(out + (size_t)(nd + node1) * 64) + lane) =
                make_float2(ma1.x + mb1.x + bx, ma1.y + mb1.y + by);
    }
}

// ---------------- host launcher ----------------

static float* fs_ptr() {
    static float* p = nullptr;
    if (!p) cudaGetSymbolAddress((void**)&p, g_fs);
    return p;
}

static inline int cdiv(long long a, long long b) { return (int)((a + b - 1) / b); }

extern "C" void kernel_launch(void* const* d_in, const int* in_sizes, int n_in,
                              void* d_out, int out_size) {
    const float* x_drug = (const float*)d_in[0];
    const float* x_prot = (const float*)d_in[1];
    const int* src_ddi = (const int*)d_in[2];
    const int* dst_ddi = (const int*)d_in[3];
    const int* src_dpi = (const int*)d_in[4];
    const int* dst_dpi = (const int*)d_in[5];
    const int* src_ppi = (const int*)d_in[6];
    const int* dst_ppi = (const int*)d_in[7];
    const float* W1_ddi = (const float*)d_in[8];
    const float* b1_ddi = (const float*)d_in[9];
    const float* W1_dpi = (const float*)d_in[10];
    const float* b1_dpi = (const float*)d_in[11];
    const float* W1_ppi = (const float*)d_in[12];
    const float* b1_ppi = (const float*)d_in[13];
    const float* W2_ddi = (const float*)d_in[14];
    const float* b2_ddi = (const float*)d_in[15];
    const float* W2_dpi = (const float*)d_in[16];
    const float* b2_dpi = (const float*)d_in[17];
    const float* W2_ppi = (const float*)d_in[18];
    const float* b2_ppi = (const float*)d_in[19];
    float* out = (float*)d_out;

    int nd = in_sizes[0] / 128;
    int np = in_sizes[1] / 128;
    int ed = in_sizes[2];
    int ep = in_sizes[4];
    int eq = in_sizes[6];

    float* S = fs_ptr();
    float* h_d   = S + F_HD;
    float* h_p   = S + F_HP;
    float* t_ddi = S + F_T_DDI;
    float* t_dpi = S + F_T_DPI;
    float* t_ppi = S + F_T_PPI;

    int emax = ed > ep ? ed : ep;
    if (eq > emax) emax = eq;
    int nmax = nd > np ? nd : np;
    int sblk = cdiv(nmax, SCAN_BLK);

    // ---- CSR build + W interleave: 3 launches ----
    int nb_count = cdiv(emax, 256);
    k_count<<<nb_count + WPREP_BLKS, 256>>>(dst_ddi, ed, dst_dpi, ep, dst_ppi, eq,
                                            W1_ddi, W1_dpi, W1_ppi,
                                            W2_ddi, W2_dpi, W2_ppi, nb_count);
    k_scan12<<<3 * sblk, 1024>>>(sblk, nd, np, np);
    k_fillfin<<<cdiv(emax, 256), 256>>>(src_ddi, dst_ddi, ed,
                                        src_dpi, dst_dpi, ep,
                                        src_ppi, dst_ppi, eq, nd, np, np);

    // ---- layer 1: fused gather + GEMM (round-12; launch index 3) ----
    int nbd1 = cdiv(nd, 16), nbp1 = cdiv(np, 16);
    k_l1<<<nbd1 + nbp1, 256>>>(x_drug, x_prot, b1_ddi, b1_dpi, b1_ppi,
                               h_d, h_p, nd, np, nbd1);

    // ---- layer 2 transforms (dual-output drug blocks) ----
    int nbA = cdiv(nd, 16), nbP = cdiv(np, 32);
    k_gemm2<<<nbA + nbP, 256>>>(h_d, h_p, t_ddi, t_dpi, t_ppi, nd, np, nbA);

    // ---- layer 2 gather + bias + concat (+ zero g_cnt for next replay) ----
    int wd = cdiv(nd, 2), wp = cdiv(np, 2);
    int nb_main = cdiv(wd + wp, 8);
    k_out<<<nb_main + ZERO_BLKS, 256>>>(t_ddi, t_dpi, t_ppi,
                                        b2_ddi, b2_dpi, b2_ppi, out, nd, np, wd, nb_main);
}